// round 7
// baseline (speedup 1.0000x reference)
#include <cuda_runtime.h>
#include <cuda_fp16.h>
#include <cstdint>
#include <math.h>

#define NN 8192
#define IN_F 128
#define OUT_F 64
#define ALPHA 0.2f
#define LOG2E 1.4426950408889634f
#define NCH 128            // 32-col chunks over a 4096-col half
#define DEPTH 4
#define APITCH 160         // adjacency smem row pitch (128B data + 32B)
#define AMAT   (128 * APITCH)          // 20480 B per matrix per chunk
#define ACH    (2 * AMAT)              // 40960 B per chunk (G+S)
#define BPITCH 80          // B tile row pitch (64B data + 16B)
#define BCH    (64 * BPITCH)           // 5120 B per chunk
#define SMEM_TOTAL (DEPTH * ACH + DEPTH * BCH)   // 184320

// ---------------- device scratch (allocation-free rule) ----------------
__device__ float  g_s1[NN];
__device__ float  g_s2[NN];
__device__ float  g_M;
__device__ __half g_hT[(size_t)OUT_F * NN];     // H^T fp16, [f][j]
__device__ float  g_num[(size_t)4 * NN * OUT_F];
__device__ float  g_den[4 * NN];

// ---------------------------------------------------------------------------
// Kernel A: h = feat @ W^T ; s1/s2 row scores ; g_hT = fp16(h)^T
// ---------------------------------------------------------------------------
__global__ __launch_bounds__(1024) void k_proj(const float* __restrict__ feat,
                                               const float* __restrict__ W,
                                               const float* __restrict__ a) {
    __shared__ float Ws[OUT_F][IN_F + 4];
    __shared__ float Fs[16][IN_F];
    __shared__ float red1[32], red2[32];
    __shared__ __half Ts[OUT_F][18];

    int tid = threadIdx.x;
    int i0  = blockIdx.x * 16;

    for (int t = tid; t < OUT_F * IN_F; t += 1024)
        Ws[t / IN_F][t % IN_F] = W[t];
    for (int t = tid; t < 16 * IN_F; t += 1024)
        Fs[t / IN_F][t % IN_F] = feat[(size_t)(i0 + t / IN_F) * IN_F + (t % IN_F)];
    __syncthreads();

    int f = tid & 63;
    int r = tid >> 6;
    float acc = 0.f;
#pragma unroll
    for (int k = 0; k < IN_F; k += 4) {
        float4 fv = *(const float4*)&Fs[r][k];
        float4 wv = *(const float4*)&Ws[f][k];
        acc += fv.x * wv.x + fv.y * wv.y + fv.z * wv.z + fv.w * wv.w;
    }

    Ts[f][r] = __float2half(acc);

    float t1 = acc * a[f];
    float t2 = acc * a[OUT_F + f];
#pragma unroll
    for (int off = 16; off; off >>= 1) {
        t1 += __shfl_xor_sync(0xffffffffu, t1, off);
        t2 += __shfl_xor_sync(0xffffffffu, t2, off);
    }
    int w = tid >> 5;
    if ((tid & 31) == 0) { red1[w] = t1; red2[w] = t2; }
    __syncthreads();
    if (tid < 16) {
        g_s1[i0 + tid] = red1[2 * tid] + red1[2 * tid + 1];
        g_s2[i0 + tid] = red2[2 * tid] + red2[2 * tid + 1];
    }
    if (tid < 512) {
        int ff = tid >> 3, u = tid & 7;
        __half2 pk = __halves2half2(Ts[ff][2 * u], Ts[ff][2 * u + 1]);
        *(__half2*)&g_hT[(size_t)ff * NN + i0 + 2 * u] = pk;
    }
}

// ---------------------------------------------------------------------------
// Kernel B: g_M = max_j s2[j]
// ---------------------------------------------------------------------------
__global__ __launch_bounds__(256) void k_max() {
    __shared__ float red[8];
    int tid = threadIdx.x;
    float m = -1e30f;
    for (int i = tid; i < NN; i += 256) m = fmaxf(m, g_s2[i]);
#pragma unroll
    for (int off = 16; off; off >>= 1)
        m = fmaxf(m, __shfl_xor_sync(0xffffffffu, m, off));
    if ((tid & 31) == 0) red[tid >> 5] = m;
    __syncthreads();
    if (tid == 0) {
        float mm = red[0];
#pragma unroll
        for (int i = 1; i < 8; i++) mm = fmaxf(mm, red[i]);
        g_M = mm;
    }
}

// ---------------------------------------------------------------------------
// Main kernel. 128 CTAs (64 row-tiles x 2 halves) x 512 threads, 1 CTA/SM.
// Adjacency + H^T staged via cp.async, 4-deep chunk pipeline; warps split
// over the two k-16 halves of each chunk (kkg), 4 split-K partials total.
// ---------------------------------------------------------------------------
__device__ __forceinline__ float2 lds64(uint32_t a) {
    float2 v;
    asm volatile("ld.shared.v2.f32 {%0,%1}, [%2];" : "=f"(v.x), "=f"(v.y) : "r"(a));
    return v;
}

__device__ __forceinline__ uint32_t score2(float2 g, float2 s, float2 z,
                                           float s1, float bn, __half2& dh) {
    float cx = (g.x + s.x) * LOG2E;
    float cy = (g.y + s.y) * LOG2E;
    float xx = s1 + z.x, xy = s1 + z.y;
    float lx = fmaxf(xx, ALPHA * xx);
    float ly = fmaxf(xy, ALPHA * xy);
    float px = (cx > 0.f) ? exp2f(fmaf(lx, cx, -bn)) : 0.f;
    float py = (cy > 0.f) ? exp2f(fmaf(ly, cy, -bn)) : 0.f;
    __half2 ph = __floats2half2_rn(px, py);
    dh = __hadd2(dh, ph);
    return *(uint32_t*)&ph;
}

__device__ __forceinline__ void mma16816(float* d, const uint32_t* a,
                                         uint32_t b0, uint32_t b1) {
    asm volatile(
        "mma.sync.aligned.m16n8k16.row.col.f32.f16.f16.f32 "
        "{%0,%1,%2,%3},{%4,%5,%6,%7},{%8,%9},{%0,%1,%2,%3};"
        : "+f"(d[0]), "+f"(d[1]), "+f"(d[2]), "+f"(d[3])
        : "r"(a[0]), "r"(a[1]), "r"(a[2]), "r"(a[3]), "r"(b0), "r"(b1));
}

__global__ __launch_bounds__(512, 1) void k_main(const float* __restrict__ geo,
                                                 const float* __restrict__ sem) {
    extern __shared__ __align__(16) char smem[];

    int tid = threadIdx.x, lane = tid & 31, w = tid >> 5;
    int r = lane >> 2, tg = lane & 3;
    int wg = w & 7, kkg = w >> 3;
    int rb = blockIdx.x >> 1, half = blockIdx.x & 1;
    int i0 = rb * 128, jbase = half * 4096;

    uint32_t abase;
    asm("{ .reg .u64 t; cvta.to.shared.u64 t, %1; cvt.u32.u64 %0, t; }"
        : "=r"(abase) : "l"(smem));
    uint32_t bbase = abase + DEPTH * ACH;

    // ---- staging maps ----
    int mat = tid >> 8, rr = (tid & 255) >> 1, hf = tid & 1;
    const float* adj_src = (mat ? sem : geo) + (size_t)(i0 + rr) * NN + jbase + hf * 16;
    uint32_t adj_dst = abase + mat * AMAT + rr * APITCH + hf * 64;
    int bn_ = tid >> 2, sg = tid & 3;
    const __half* b_src = g_hT + (size_t)bn_ * NN + jbase + sg * 8;
    uint32_t b_dst = bbase + bn_ * BPITCH + sg * 16;

    // ---- consume maps ----
    uint32_t rowA0 = (uint32_t)(16 * wg + r) * APITCH;
    uint32_t rowA1 = rowA0 + 8 * APITCH;
    uint32_t colA  = (uint32_t)(kkg * 16 + 2 * tg) * 4;
    int ldrow = ((lane >> 4) & 1) * 8 + (lane & 7);
    int ldcol = ((lane >> 3) & 1) * 16;
    uint32_t ldoff = (uint32_t)ldrow * BPITCH + kkg * 32 + ldcol;
    const float* s2p = g_s2 + jbase + kkg * 16 + 2 * tg;

    int row0 = i0 + 16 * wg + r;
    float Mv  = g_M;
    float s10 = g_s1[row0], s11 = g_s1[row0 + 8];
    float bn0 = fmaxf(0.f, 2.f * (s10 + Mv)) * LOG2E;
    float bn1 = fmaxf(0.f, 2.f * (s11 + Mv)) * LOG2E;

    float acc[8][4];
#pragma unroll
    for (int i = 0; i < 8; i++)
#pragma unroll
        for (int j = 0; j < 4; j++) acc[i][j] = 0.f;
    float dloc[2] = {0.f, 0.f};

    // ---- prologue: stage chunks 0..2 ----
#pragma unroll
    for (int pc = 0; pc < DEPTH - 1; pc++) {
        const float* s0 = adj_src + (size_t)pc * 32;
        uint32_t d0 = adj_dst + pc * ACH;
#pragma unroll
        for (int p = 0; p < 4; p++)
            asm volatile("cp.async.cg.shared.global [%0], [%1], 16;"
                         :: "r"(d0 + p * 16), "l"(s0 + p * 4));
        if (tid < 256)
            asm volatile("cp.async.cg.shared.global [%0], [%1], 16;"
                         :: "r"(b_dst + pc * BCH), "l"(b_src + (size_t)pc * 32));
        asm volatile("cp.async.commit_group;");
    }

    for (int c = 0; c < NCH; c++) {
        asm volatile("cp.async.wait_group %0;" :: "n"(DEPTH - 2));
        __syncthreads();   // chunk c staged & visible; chunk c-1 fully consumed

        // stage chunk c+3 into buffer (c+3)&3 (the one freed by c-1)
        if (c + DEPTH - 1 < NCH) {
            int cs = c + DEPTH - 1;
            const float* s0 = adj_src + (size_t)cs * 32;
            uint32_t d0 = adj_dst + (cs & (DEPTH - 1)) * ACH;
#pragma unroll
            for (int p = 0; p < 4; p++)
                asm volatile("cp.async.cg.shared.global [%0], [%1], 16;"
                             :: "r"(d0 + p * 16), "l"(s0 + p * 4));
            if (tid < 256)
                asm volatile("cp.async.cg.shared.global [%0], [%1], 16;"
                             :: "r"(b_dst + (cs & (DEPTH - 1)) * BCH),
                                "l"(b_src + (size_t)cs * 32));
        }
        asm volatile("cp.async.commit_group;");   // always: keeps group count fixed

        // ---- consume chunk c ----
        uint32_t ab = abase + (c & (DEPTH - 1)) * ACH;
        float2 z0 = *(const float2*)(s2p + c * 32);
        float2 z1 = *(const float2*)(s2p + c * 32 + 8);

        float2 g00 = lds64(ab + rowA0 + colA);
        float2 g01 = lds64(ab + rowA0 + colA + 32);
        float2 g10 = lds64(ab + rowA1 + colA);
        float2 g11 = lds64(ab + rowA1 + colA + 32);
        float2 s00 = lds64(ab + AMAT + rowA0 + colA);
        float2 s01 = lds64(ab + AMAT + rowA0 + colA + 32);
        float2 s10v = lds64(ab + AMAT + rowA1 + colA);
        float2 s11v = lds64(ab + AMAT + rowA1 + colA + 32);

        __half2 dh0 = __float2half2_rn(0.f), dh1 = dh0;
        uint32_t af[4];
        af[0] = score2(g00, s00,  z0, s10, bn0, dh0);
        af[1] = score2(g10, s10v, z0, s11, bn1, dh1);
        af[2] = score2(g01, s01,  z1, s10, bn0, dh0);
        af[3] = score2(g11, s11v, z1, s11, bn1, dh1);

        float2 d0f = __half22float2(dh0);
        float2 d1f = __half22float2(dh1);
        dloc[0] += d0f.x + d0f.y;
        dloc[1] += d1f.x + d1f.y;

        uint32_t bb = bbase + (c & (DEPTH - 1)) * BCH + ldoff;
#pragma unroll
        for (int t = 0; t < 4; t++) {
            uint32_t b0, b1, b2, b3;
            asm volatile(
                "ldmatrix.sync.aligned.m8n8.x4.shared.b16 {%0,%1,%2,%3}, [%4];"
                : "=r"(b0), "=r"(b1), "=r"(b2), "=r"(b3)
                : "r"(bb + (uint32_t)t * 16 * BPITCH));
            mma16816(acc[2 * t],     af, b0, b1);
            mma16816(acc[2 * t + 1], af, b2, b3);
        }
    }

    // ---- epilogue ----
    int part = half * 2 + kkg;
#pragma unroll
    for (int ro = 0; ro < 2; ro++) {
        float v = dloc[ro];
        v += __shfl_xor_sync(0xffffffffu, v, 1);
        v += __shfl_xor_sync(0xffffffffu, v, 2);
        dloc[ro] = v;
    }
    if (tg == 0) {
        g_den[part * NN + row0]     = dloc[0];
        g_den[part * NN + row0 + 8] = dloc[1];
    }

    float* dst0 = g_num + ((size_t)part * NN + row0) * OUT_F;
    float* dst1 = g_num + ((size_t)part * NN + row0 + 8) * OUT_F;
#pragma unroll
    for (int t = 0; t < 8; t++) {
        int n0 = 8 * t + 2 * tg;
        *(float2*)(dst0 + n0) = make_float2(acc[t][0], acc[t][1]);
        *(float2*)(dst1 + n0) = make_float2(acc[t][2], acc[t][3]);
    }
}

// ---------------------------------------------------------------------------
// Combine split-K partials: out = elu(sum(n)/sum(d))
// ---------------------------------------------------------------------------
__global__ __launch_bounds__(256) void k_fin(float* __restrict__ out) {
    int idx = blockIdx.x * 256 + threadIdx.x;
    int row = idx >> 4, qq = idx & 15;
    float den = g_den[row] + g_den[NN + row] + g_den[2 * NN + row] + g_den[3 * NN + row];
    float inv = 1.0f / den;
    float4 n0 = *(const float4*)&g_num[(size_t)row * OUT_F + 4 * qq];
    float4 n1 = *(const float4*)&g_num[(size_t)(NN + row) * OUT_F + 4 * qq];
    float4 n2 = *(const float4*)&g_num[(size_t)(2 * NN + row) * OUT_F + 4 * qq];
    float4 n3 = *(const float4*)&g_num[(size_t)(3 * NN + row) * OUT_F + 4 * qq];
    float4 o;
    float v;
    v = (n0.x + n1.x + n2.x + n3.x) * inv; o.x = (v > 0.f) ? v : expm1f(v);
    v = (n0.y + n1.y + n2.y + n3.y) * inv; o.y = (v > 0.f) ? v : expm1f(v);
    v = (n0.z + n1.z + n2.z + n3.z) * inv; o.z = (v > 0.f) ? v : expm1f(v);
    v = (n0.w + n1.w + n2.w + n3.w) * inv; o.w = (v > 0.f) ? v : expm1f(v);
    *(float4*)&out[(size_t)row * OUT_F + 4 * qq] = o;
}

// ---------------------------------------------------------------------------
extern "C" void kernel_launch(void* const* d_in, const int* in_sizes, int n_in,
                              void* d_out, int out_size) {
    const float* geo  = (const float*)d_in[0];
    const float* sem  = (const float*)d_in[1];
    const float* feat = (const float*)d_in[2];
    const float* W    = (const float*)d_in[3];
    const float* a    = (const float*)d_in[4];
    float* out = (float*)d_out;

    cudaFuncSetAttribute(k_main, cudaFuncAttributeMaxDynamicSharedMemorySize, SMEM_TOTAL);

    k_proj<<<NN / 16, 1024>>>(feat, W, a);
    k_max<<<1, 256>>>();
    k_main<<<128, 512, SMEM_TOTAL>>>(geo, sem);
    k_fin<<<512, 256>>>(out);
}

// round 8
// speedup vs baseline: 1.2793x; 1.2793x over previous
#include <cuda_runtime.h>
#include <cuda_fp16.h>
#include <cstdint>
#include <math.h>

#define NN 8192
#define IN_F 128
#define OUT_F 64
#define ALPHA 0.2f
#define LOG2E 1.4426950408889634f
#define NCH 128            // 32-col chunks over a 4096-col half
#define SBCH 8             // chunks per B superblock (256 cols)
#define BPITCH 528         // B smem row pitch -> 16B rotation, conflict-free
#define BBYTES (64 * BPITCH)
#define SPITCH 80          // score tile pitch -> 16B rotation, conflict-free
#define SWARP (2 * 16 * SPITCH)      // per-warp double-buffered score tile
#define SMEMT (2 * BBYTES + 8 * SWARP)   // 67584 + 20480 = 88064

// ---------------- device scratch (allocation-free rule) ----------------
__device__ float  g_s1[NN];
__device__ float  g_s2[NN];
__device__ float  g_M;
__device__ __half g_hT[(size_t)OUT_F * NN];     // H^T fp16, [f][j]
__device__ float  g_num[(size_t)2 * NN * OUT_F];
__device__ float  g_den[2 * NN];

// ---------------------------------------------------------------------------
// Kernel A: h = feat @ W^T ; s1/s2 row scores ; g_hT = fp16(h)^T
// ---------------------------------------------------------------------------
__global__ __launch_bounds__(1024) void k_proj(const float* __restrict__ feat,
                                               const float* __restrict__ W,
                                               const float* __restrict__ a) {
    __shared__ float Ws[OUT_F][IN_F + 4];
    __shared__ float Fs[16][IN_F];
    __shared__ float red1[32], red2[32];
    __shared__ __half Ts[OUT_F][18];

    int tid = threadIdx.x;
    int i0  = blockIdx.x * 16;

    for (int t = tid; t < OUT_F * IN_F; t += 1024)
        Ws[t / IN_F][t % IN_F] = W[t];
    for (int t = tid; t < 16 * IN_F; t += 1024)
        Fs[t / IN_F][t % IN_F] = feat[(size_t)(i0 + t / IN_F) * IN_F + (t % IN_F)];
    __syncthreads();

    int f = tid & 63;
    int r = tid >> 6;
    float acc = 0.f;
#pragma unroll
    for (int k = 0; k < IN_F; k += 4) {
        float4 fv = *(const float4*)&Fs[r][k];
        float4 wv = *(const float4*)&Ws[f][k];
        acc += fv.x * wv.x + fv.y * wv.y + fv.z * wv.z + fv.w * wv.w;
    }

    Ts[f][r] = __float2half(acc);

    float t1 = acc * a[f];
    float t2 = acc * a[OUT_F + f];
#pragma unroll
    for (int off = 16; off; off >>= 1) {
        t1 += __shfl_xor_sync(0xffffffffu, t1, off);
        t2 += __shfl_xor_sync(0xffffffffu, t2, off);
    }
    int w = tid >> 5;
    if ((tid & 31) == 0) { red1[w] = t1; red2[w] = t2; }
    __syncthreads();
    if (tid < 16) {
        g_s1[i0 + tid] = red1[2 * tid] + red1[2 * tid + 1];
        g_s2[i0 + tid] = red2[2 * tid] + red2[2 * tid + 1];
    }
    if (tid < 512) {
        int ff = tid >> 3, u = tid & 7;
        __half2 pk = __halves2half2(Ts[ff][2 * u], Ts[ff][2 * u + 1]);
        *(__half2*)&g_hT[(size_t)ff * NN + i0 + 2 * u] = pk;
    }
}

// ---------------------------------------------------------------------------
// Kernel B: g_M = max_j s2[j]
// ---------------------------------------------------------------------------
__global__ __launch_bounds__(256) void k_max() {
    __shared__ float red[8];
    int tid = threadIdx.x;
    float m = -1e30f;
    for (int i = tid; i < NN; i += 256) m = fmaxf(m, g_s2[i]);
#pragma unroll
    for (int off = 16; off; off >>= 1)
        m = fmaxf(m, __shfl_xor_sync(0xffffffffu, m, off));
    if ((tid & 31) == 0) red[tid >> 5] = m;
    __syncthreads();
    if (tid == 0) {
        float mm = red[0];
#pragma unroll
        for (int i = 1; i < 8; i++) mm = fmaxf(mm, red[i]);
        g_M = mm;
    }
}

// ---------------------------------------------------------------------------
// Main kernel. 128 CTAs (64 row-tiles x 2 halves) x 256 threads.
// Coalesced LDG.128 adjacency (4 lines/instr), scores in coalesced layout,
// warp-local smem transpose -> ldmatrix A-frags, HMMA m16n8k16.
// ---------------------------------------------------------------------------
struct ChunkBuf {
    float4 G[4];
    float4 S[4];
    float4 Z;
};

__device__ __forceinline__ void load_chunk(const float* __restrict__ gp0,
                                           const float* __restrict__ sp0,
                                           const float* __restrict__ s2p,
                                           int c, ChunkBuf& b) {
    size_t off = (size_t)c * 32;
#pragma unroll
    for (int i = 0; i < 4; i++) {
        b.G[i] = __ldcs((const float4*)(gp0 + off + (size_t)(4 * i) * NN));
        b.S[i] = __ldcs((const float4*)(sp0 + off + (size_t)(4 * i) * NN));
    }
    b.Z = *(const float4*)(s2p + off);
}

__device__ __forceinline__ void mma16816(float* d, const uint32_t* a,
                                         uint32_t b0, uint32_t b1) {
    asm volatile(
        "mma.sync.aligned.m16n8k16.row.col.f32.f16.f16.f32 "
        "{%0,%1,%2,%3},{%4,%5,%6,%7},{%8,%9},{%0,%1,%2,%3};"
        : "+f"(d[0]), "+f"(d[1]), "+f"(d[2]), "+f"(d[3])
        : "r"(a[0]), "r"(a[1]), "r"(a[2]), "r"(a[3]), "r"(b0), "r"(b1));
}

__device__ __forceinline__ void proc_chunk(int c, ChunkBuf& cur, ChunkBuf& nxt,
                                           const float* gp0, const float* sp0,
                                           const float* s2p,
                                           uint32_t sts0, uint32_t lda0, uint32_t ldb,
                                           const float (&s1v)[4], const float (&bnv)[4],
                                           float (&dloc)[4], float (&acc)[8][4]) {
    // 1. prefetch next chunk's adjacency (coalesced LDG.128)
    int cn = (c + 1 < NCH) ? c + 1 : 0;
    load_chunk(gp0, sp0, s2p, cn, nxt);

    uint32_t bufo = (uint32_t)(c & 1) * (16 * SPITCH);

    // 2. scores in coalesced layout (4 rows x 4 cols per thread) -> smem
    __half2 dh[4];
#pragma unroll
    for (int i = 0; i < 4; i++) {
        float4 g = cur.G[i], s = cur.S[i];
        float clx = (g.x + s.x) * LOG2E;
        float cly = (g.y + s.y) * LOG2E;
        float clz = (g.z + s.z) * LOG2E;
        float clw = (g.w + s.w) * LOG2E;
        float s1 = s1v[i], bn = bnv[i];
        float x0 = s1 + cur.Z.x, x1 = s1 + cur.Z.y;
        float x2 = s1 + cur.Z.z, x3 = s1 + cur.Z.w;
        float l0 = fmaxf(x0, ALPHA * x0), l1 = fmaxf(x1, ALPHA * x1);
        float l2 = fmaxf(x2, ALPHA * x2), l3 = fmaxf(x3, ALPHA * x3);
        float p0 = (clx > 0.f) ? exp2f(fmaf(l0, clx, -bn)) : 0.f;
        float p1 = (cly > 0.f) ? exp2f(fmaf(l1, cly, -bn)) : 0.f;
        float p2 = (clz > 0.f) ? exp2f(fmaf(l2, clz, -bn)) : 0.f;
        float p3 = (clw > 0.f) ? exp2f(fmaf(l3, clw, -bn)) : 0.f;
        __half2 lo = __floats2half2_rn(p0, p1);
        __half2 hi = __floats2half2_rn(p2, p3);
        dh[i] = __hadd2(lo, hi);
        asm volatile("st.shared.v2.b32 [%0], {%1,%2};"
                     :: "r"(sts0 + bufo + (uint32_t)(4 * i) * SPITCH),
                        "r"(*(uint32_t*)&lo), "r"(*(uint32_t*)&hi));
    }
#pragma unroll
    for (int i = 0; i < 4; i++) {
        float2 d = __half22float2(dh[i]);
        dloc[i] += d.x + d.y;
    }

    __syncwarp();

    // 3. A-frags via ldmatrix from own warp's tile
    uint32_t af[2][4];
    uint32_t la = lda0 + bufo;
#pragma unroll
    for (int kk = 0; kk < 2; kk++)
        asm volatile(
            "ldmatrix.sync.aligned.m8n8.x4.shared.b16 {%0,%1,%2,%3}, [%4];"
            : "=r"(af[kk][0]), "=r"(af[kk][1]), "=r"(af[kk][2]), "=r"(af[kk][3])
            : "r"(la + kk * 32));

    // 4. B-frags + 16 HMMA
    uint32_t bb = ldb + (uint32_t)(c & (SBCH - 1)) * 64;
#pragma unroll
    for (int kk = 0; kk < 2; kk++) {
#pragma unroll
        for (int t = 0; t < 4; t++) {
            uint32_t b0, b1, b2, b3;
            asm volatile(
                "ldmatrix.sync.aligned.m8n8.x4.shared.b16 {%0,%1,%2,%3}, [%4];"
                : "=r"(b0), "=r"(b1), "=r"(b2), "=r"(b3)
                : "r"(bb + (uint32_t)t * 16 * BPITCH + kk * 32));
            mma16816(acc[2 * t],     af[kk], b0, b1);
            mma16816(acc[2 * t + 1], af[kk], b2, b3);
        }
    }
}

__global__ __launch_bounds__(256, 1) void k_main(const float* __restrict__ geo,
                                                 const float* __restrict__ sem) {
    extern __shared__ __align__(16) char smem[];

    int tid = threadIdx.x, lane = tid & 31, w = tid >> 5;
    int rb = blockIdx.x >> 1, half = blockIdx.x & 1;
    int i0 = rb * 128, jbase = half * 4096;

    int subrow = lane >> 3, colseg = (lane & 7) * 4;

    const float* gp0 = geo + (size_t)(i0 + 16 * w + subrow) * NN + jbase + colseg;
    const float* sp0 = sem + (size_t)(i0 + 16 * w + subrow) * NN + jbase + colseg;
    const float* s2p = g_s2 + jbase + colseg;

    float Mv = g_M;
    float s1v[4], bnv[4];
#pragma unroll
    for (int i = 0; i < 4; i++) {
        s1v[i] = g_s1[i0 + 16 * w + 4 * i + subrow];
        bnv[i] = fmaxf(0.f, 2.f * (s1v[i] + Mv)) * LOG2E;
    }

    uint32_t smem0;
    asm("{ .reg .u64 t; cvta.to.shared.u64 t, %1; cvt.u32.u64 %0, t; }"
        : "=r"(smem0) : "l"(smem));
    uint32_t bbase = smem0;
    uint32_t sbuf  = smem0 + 2 * BBYTES + w * SWARP;

    // score STS base (rows 4i+subrow at colseg)
    uint32_t sts0 = sbuf + (uint32_t)subrow * SPITCH + (uint32_t)colseg * 2;
    // ldmatrix A base: lanes 0-7 rows 0-7 seg0, 8-15 rows 8-15 seg0, 16-23 rows 0-7 seg1...
    uint32_t lda0 = sbuf + (uint32_t)(lane & 15) * SPITCH + (uint32_t)(lane >> 4) * 16;
    // ldmatrix B base
    int ldrow = ((lane >> 4) & 1) * 8 + (lane & 7);
    int ldcol = ((lane >> 3) & 1) * 16;
    uint32_t ldb0 = bbase + (uint32_t)ldrow * BPITCH + ldcol;

    // B staging map
    int srow = tid >> 5, sseg = tid & 31;
    const __half* bsrc = g_hT + (size_t)srow * NN + jbase + sseg * 8;
    uint32_t bdst = bbase + (uint32_t)srow * BPITCH + sseg * 16;

    float acc[8][4];
#pragma unroll
    for (int i = 0; i < 8; i++)
#pragma unroll
        for (int j = 0; j < 4; j++) acc[i][j] = 0.f;
    float dloc[4] = {0.f, 0.f, 0.f, 0.f};

    // prologue: stage B superblock 0
#pragma unroll
    for (int p = 0; p < 8; p++)
        asm volatile("cp.async.cg.shared.global [%0], [%1], 16;"
                     :: "r"(bdst + (uint32_t)(8 * p) * BPITCH),
                        "l"(bsrc + (size_t)(8 * p) * NN));
    asm volatile("cp.async.commit_group;");
    asm volatile("cp.async.wait_group 0;");

    ChunkBuf A0, A1;
    load_chunk(gp0, sp0, s2p, 0, A0);
    __syncthreads();

    int c = 0;
    for (int sb = 0; sb < NCH / SBCH; sb++) {
        if (sb + 1 < NCH / SBCH) {
            int jblk = (sb + 1) * (SBCH * 32);
            uint32_t bd = bdst + (uint32_t)((sb + 1) & 1) * BBYTES;
#pragma unroll
            for (int p = 0; p < 8; p++)
                asm volatile("cp.async.cg.shared.global [%0], [%1], 16;"
                             :: "r"(bd + (uint32_t)(8 * p) * BPITCH),
                                "l"(bsrc + (size_t)(8 * p) * NN + jblk));
            asm volatile("cp.async.commit_group;");
        }

        uint32_t ldb = ldb0 + (uint32_t)(sb & 1) * BBYTES;
#pragma unroll 2
        for (int cc = 0; cc < SBCH; cc += 2) {
            proc_chunk(c,     A0, A1, gp0, sp0, s2p, sts0, lda0, ldb, s1v, bnv, dloc, acc);
            proc_chunk(c + 1, A1, A0, gp0, sp0, s2p, sts0, lda0, ldb, s1v, bnv, dloc, acc);
            c += 2;
        }

        asm volatile("cp.async.wait_group 0;");
        __syncthreads();
    }

    // ---- epilogue ----
    // denominators: reduce over the 8 col-groups (low 3 lane bits)
#pragma unroll
    for (int i = 0; i < 4; i++) {
        float v = dloc[i];
        v += __shfl_xor_sync(0xffffffffu, v, 1);
        v += __shfl_xor_sync(0xffffffffu, v, 2);
        v += __shfl_xor_sync(0xffffffffu, v, 4);
        dloc[i] = v;
    }
    if ((lane & 7) == 0) {
#pragma unroll
        for (int i = 0; i < 4; i++)
            g_den[half * NN + i0 + 16 * w + 4 * i + subrow] = dloc[i];
    }

    // numerator partials: c-frag layout (r = lane>>2, tg = lane&3)
    int r = lane >> 2, tg = lane & 3;
    int row0 = i0 + 16 * w + r;
    float* dst0 = g_num + ((size_t)half * NN + row0) * OUT_F;
    float* dst1 = g_num + ((size_t)half * NN + row0 + 8) * OUT_F;
#pragma unroll
    for (int t = 0; t < 8; t++) {
        int n0 = 8 * t + 2 * tg;
        *(float2*)(dst0 + n0) = make_float2(acc[t][0], acc[t][1]);
        *(float2*)(dst1 + n0) = make_float2(acc[t][2], acc[t][3]);
    }
}

// ---------------------------------------------------------------------------
// Combine split-K partials: out = elu((n0+n1)/(d0+d1))
// ---------------------------------------------------------------------------
__global__ __launch_bounds__(256) void k_fin(float* __restrict__ out) {
    int idx = blockIdx.x * 256 + threadIdx.x;
    int row = idx >> 4, q = idx & 15;
    float inv = 1.0f / (g_den[row] + g_den[NN + row]);
    float4 n0 = *(const float4*)&g_num[(size_t)row * OUT_F + 4 * q];
    float4 n1 = *(const float4*)&g_num[(size_t)(NN + row) * OUT_F + 4 * q];
    float4 o;
    float v;
    v = (n0.x + n1.x) * inv; o.x = (v > 0.f) ? v : expm1f(v);
    v = (n0.y + n1.y) * inv; o.y = (v > 0.f) ? v : expm1f(v);
    v = (n0.z + n1.z) * inv; o.z = (v > 0.f) ? v : expm1f(v);
    v = (n0.w + n1.w) * inv; o.w = (v > 0.f) ? v : expm1f(v);
    *(float4*)&out[(size_t)row * OUT_F + 4 * q] = o;
}

// ---------------------------------------------------------------------------
extern "C" void kernel_launch(void* const* d_in, const int* in_sizes, int n_in,
                              void* d_out, int out_size) {
    const float* geo  = (const float*)d_in[0];
    const float* sem  = (const float*)d_in[1];
    const float* feat = (const float*)d_in[2];
    const float* W    = (const float*)d_in[3];
    const float* a    = (const float*)d_in[4];
    float* out = (float*)d_out;

    cudaFuncSetAttribute(k_main, cudaFuncAttributeMaxDynamicSharedMemorySize, SMEMT);

    k_proj<<<NN / 16, 1024>>>(feat, W, a);
    k_max<<<1, 256>>>();
    k_main<<<128, 256, SMEMT>>>(geo, sem);
    k_fin<<<512, 256>>>(out);
}

// round 9
// speedup vs baseline: 1.6191x; 1.2655x over previous
#include <cuda_runtime.h>
#include <cuda_fp16.h>
#include <cstdint>
#include <math.h>

#define NN 8192
#define IN_F 128
#define OUT_F 64
#define ALPHA 0.2f
#define LOG2E 1.4426950408889634f
#define NCH 64             // 32-col chunks over a 2048-col quarter
#define SBCH 8             // chunks per B superblock (256 cols)
#define BPITCH 528         // B smem row pitch -> 16B rotation, conflict-free
#define BBYTES (64 * BPITCH)
#define SPITCH 80          // score tile pitch -> 16B rotation, conflict-free
#define SWARP (2 * 16 * SPITCH)      // per-warp double-buffered score tile
#define SMEMT (2 * BBYTES + 8 * SWARP)   // 88064 B -> 2 CTAs/SM

// ---------------- device scratch (allocation-free rule) ----------------
__device__ float  g_s1[NN];
__device__ float  g_s2[NN];
__device__ float  g_M;
__device__ __half g_hT[(size_t)OUT_F * NN];     // H^T fp16, [f][j]
__device__ float  g_num[(size_t)4 * NN * OUT_F];
__device__ float  g_den[4 * NN];

// ---------------------------------------------------------------------------
// Kernel A: h = feat @ W^T ; s1/s2 row scores ; g_hT = fp16(h)^T
// ---------------------------------------------------------------------------
__global__ __launch_bounds__(1024) void k_proj(const float* __restrict__ feat,
                                               const float* __restrict__ W,
                                               const float* __restrict__ a) {
    __shared__ float Ws[OUT_F][IN_F + 4];
    __shared__ float Fs[16][IN_F];
    __shared__ float red1[32], red2[32];
    __shared__ __half Ts[OUT_F][18];

    int tid = threadIdx.x;
    int i0  = blockIdx.x * 16;

    for (int t = tid; t < OUT_F * IN_F; t += 1024)
        Ws[t / IN_F][t % IN_F] = W[t];
    for (int t = tid; t < 16 * IN_F; t += 1024)
        Fs[t / IN_F][t % IN_F] = feat[(size_t)(i0 + t / IN_F) * IN_F + (t % IN_F)];
    __syncthreads();

    int f = tid & 63;
    int r = tid >> 6;
    float acc = 0.f;
#pragma unroll
    for (int k = 0; k < IN_F; k += 4) {
        float4 fv = *(const float4*)&Fs[r][k];
        float4 wv = *(const float4*)&Ws[f][k];
        acc += fv.x * wv.x + fv.y * wv.y + fv.z * wv.z + fv.w * wv.w;
    }

    Ts[f][r] = __float2half(acc);

    float t1 = acc * a[f];
    float t2 = acc * a[OUT_F + f];
#pragma unroll
    for (int off = 16; off; off >>= 1) {
        t1 += __shfl_xor_sync(0xffffffffu, t1, off);
        t2 += __shfl_xor_sync(0xffffffffu, t2, off);
    }
    int w = tid >> 5;
    if ((tid & 31) == 0) { red1[w] = t1; red2[w] = t2; }
    __syncthreads();
    if (tid < 16) {
        g_s1[i0 + tid] = red1[2 * tid] + red1[2 * tid + 1];
        g_s2[i0 + tid] = red2[2 * tid] + red2[2 * tid + 1];
    }
    if (tid < 512) {
        int ff = tid >> 3, u = tid & 7;
        __half2 pk = __halves2half2(Ts[ff][2 * u], Ts[ff][2 * u + 1]);
        *(__half2*)&g_hT[(size_t)ff * NN + i0 + 2 * u] = pk;
    }
}

// ---------------------------------------------------------------------------
// Kernel B: g_M = max_j s2[j]
// ---------------------------------------------------------------------------
__global__ __launch_bounds__(256) void k_max() {
    __shared__ float red[8];
    int tid = threadIdx.x;
    float m = -1e30f;
    for (int i = tid; i < NN; i += 256) m = fmaxf(m, g_s2[i]);
#pragma unroll
    for (int off = 16; off; off >>= 1)
        m = fmaxf(m, __shfl_xor_sync(0xffffffffu, m, off));
    if ((tid & 31) == 0) red[tid >> 5] = m;
    __syncthreads();
    if (tid == 0) {
        float mm = red[0];
#pragma unroll
        for (int i = 1; i < 8; i++) mm = fmaxf(mm, red[i]);
        g_M = mm;
    }
}

// ---------------------------------------------------------------------------
// Main kernel. 256 CTAs (64 row-tiles x 4 quarters) x 256 threads, 2 CTAs/SM.
// Coalesced LDG.128 adjacency, warp-local score transpose -> ldmatrix A-frags,
// HMMA m16n8k16, B superblocks via cp.async.
// ---------------------------------------------------------------------------
struct ChunkBuf {
    float4 G[4];
    float4 S[4];
    float4 Z;
};

__device__ __forceinline__ void load_chunk(const float* __restrict__ gp0,
                                           const float* __restrict__ sp0,
                                           const float* __restrict__ s2p,
                                           int c, ChunkBuf& b) {
    size_t off = (size_t)c * 32;
#pragma unroll
    for (int i = 0; i < 4; i++) {
        b.G[i] = __ldcs((const float4*)(gp0 + off + (size_t)(4 * i) * NN));
        b.S[i] = __ldcs((const float4*)(sp0 + off + (size_t)(4 * i) * NN));
    }
    b.Z = *(const float4*)(s2p + off);
}

__device__ __forceinline__ void mma16816(float* d, const uint32_t* a,
                                         uint32_t b0, uint32_t b1) {
    asm volatile(
        "mma.sync.aligned.m16n8k16.row.col.f32.f16.f16.f32 "
        "{%0,%1,%2,%3},{%4,%5,%6,%7},{%8,%9},{%0,%1,%2,%3};"
        : "+f"(d[0]), "+f"(d[1]), "+f"(d[2]), "+f"(d[3])
        : "r"(a[0]), "r"(a[1]), "r"(a[2]), "r"(a[3]), "r"(b0), "r"(b1));
}

__device__ __forceinline__ void proc_chunk(int c, ChunkBuf& cur, ChunkBuf& nxt,
                                           const float* gp0, const float* sp0,
                                           const float* s2p,
                                           uint32_t sts0, uint32_t lda0, uint32_t ldb,
                                           const float (&s1v)[4], const float (&bnv)[4],
                                           float (&dloc)[4], float (&acc)[8][4]) {
    // 1. prefetch next chunk's adjacency (coalesced LDG.128)
    int cn = (c + 1 < NCH) ? c + 1 : 0;
    load_chunk(gp0, sp0, s2p, cn, nxt);

    uint32_t bufo = (uint32_t)(c & 1) * (16 * SPITCH);

    // 2. scores in coalesced layout (4 rows x 4 cols per thread) -> smem
    __half2 dh[4];
#pragma unroll
    for (int i = 0; i < 4; i++) {
        float4 g = cur.G[i], s = cur.S[i];
        float clx = (g.x + s.x) * LOG2E;
        float cly = (g.y + s.y) * LOG2E;
        float clz = (g.z + s.z) * LOG2E;
        float clw = (g.w + s.w) * LOG2E;
        float s1 = s1v[i], bn = bnv[i];
        float x0 = s1 + cur.Z.x, x1 = s1 + cur.Z.y;
        float x2 = s1 + cur.Z.z, x3 = s1 + cur.Z.w;
        float l0 = fmaxf(x0, ALPHA * x0), l1 = fmaxf(x1, ALPHA * x1);
        float l2 = fmaxf(x2, ALPHA * x2), l3 = fmaxf(x3, ALPHA * x3);
        float p0 = (clx > 0.f) ? exp2f(fmaf(l0, clx, -bn)) : 0.f;
        float p1 = (cly > 0.f) ? exp2f(fmaf(l1, cly, -bn)) : 0.f;
        float p2 = (clz > 0.f) ? exp2f(fmaf(l2, clz, -bn)) : 0.f;
        float p3 = (clw > 0.f) ? exp2f(fmaf(l3, clw, -bn)) : 0.f;
        __half2 lo = __floats2half2_rn(p0, p1);
        __half2 hi = __floats2half2_rn(p2, p3);
        dh[i] = __hadd2(lo, hi);
        asm volatile("st.shared.v2.b32 [%0], {%1,%2};"
                     :: "r"(sts0 + bufo + (uint32_t)(4 * i) * SPITCH),
                        "r"(*(uint32_t*)&lo), "r"(*(uint32_t*)&hi));
    }
#pragma unroll
    for (int i = 0; i < 4; i++) {
        float2 d = __half22float2(dh[i]);
        dloc[i] += d.x + d.y;
    }

    __syncwarp();

    // 3. A-frags via ldmatrix from own warp's tile
    uint32_t af[2][4];
    uint32_t la = lda0 + bufo;
#pragma unroll
    for (int kk = 0; kk < 2; kk++)
        asm volatile(
            "ldmatrix.sync.aligned.m8n8.x4.shared.b16 {%0,%1,%2,%3}, [%4];"
            : "=r"(af[kk][0]), "=r"(af[kk][1]), "=r"(af[kk][2]), "=r"(af[kk][3])
            : "r"(la + kk * 32));

    // 4. B-frags + 16 HMMA
    uint32_t bb = ldb + (uint32_t)(c & (SBCH - 1)) * 64;
#pragma unroll
    for (int kk = 0; kk < 2; kk++) {
#pragma unroll
        for (int t = 0; t < 4; t++) {
            uint32_t b0, b1, b2, b3;
            asm volatile(
                "ldmatrix.sync.aligned.m8n8.x4.shared.b16 {%0,%1,%2,%3}, [%4];"
                : "=r"(b0), "=r"(b1), "=r"(b2), "=r"(b3)
                : "r"(bb + (uint32_t)t * 16 * BPITCH + kk * 32));
            mma16816(acc[2 * t],     af[kk], b0, b1);
            mma16816(acc[2 * t + 1], af[kk], b2, b3);
        }
    }
}

__global__ __launch_bounds__(256, 2) void k_main(const float* __restrict__ geo,
                                                 const float* __restrict__ sem) {
    extern __shared__ __align__(16) char smem[];

    int tid = threadIdx.x, lane = tid & 31, w = tid >> 5;
    int rb = blockIdx.x >> 2, q = blockIdx.x & 3;
    int i0 = rb * 128, jbase = q * 2048;

    int subrow = lane >> 3, colseg = (lane & 7) * 4;

    const float* gp0 = geo + (size_t)(i0 + 16 * w + subrow) * NN + jbase + colseg;
    const float* sp0 = sem + (size_t)(i0 + 16 * w + subrow) * NN + jbase + colseg;
    const float* s2p = g_s2 + jbase + colseg;

    float Mv = g_M;
    float s1v[4], bnv[4];
#pragma unroll
    for (int i = 0; i < 4; i++) {
        s1v[i] = g_s1[i0 + 16 * w + 4 * i + subrow];
        bnv[i] = fmaxf(0.f, 2.f * (s1v[i] + Mv)) * LOG2E;
    }

    uint32_t smem0;
    asm("{ .reg .u64 t; cvta.to.shared.u64 t, %1; cvt.u32.u64 %0, t; }"
        : "=r"(smem0) : "l"(smem));
    uint32_t bbase = smem0;
    uint32_t sbuf  = smem0 + 2 * BBYTES + w * SWARP;

    uint32_t sts0 = sbuf + (uint32_t)subrow * SPITCH + (uint32_t)colseg * 2;
    uint32_t lda0 = sbuf + (uint32_t)(lane & 15) * SPITCH + (uint32_t)(lane >> 4) * 16;
    int ldrow = ((lane >> 4) & 1) * 8 + (lane & 7);
    int ldcol = ((lane >> 3) & 1) * 16;
    uint32_t ldb0 = bbase + (uint32_t)ldrow * BPITCH + ldcol;

    // B staging map
    int srow = tid >> 5, sseg = tid & 31;
    const __half* bsrc = g_hT + (size_t)srow * NN + jbase + sseg * 8;
    uint32_t bdst = bbase + (uint32_t)srow * BPITCH + sseg * 16;

    float acc[8][4];
#pragma unroll
    for (int i = 0; i < 8; i++)
#pragma unroll
        for (int j = 0; j < 4; j++) acc[i][j] = 0.f;
    float dloc[4] = {0.f, 0.f, 0.f, 0.f};

    // prologue: stage B superblock 0
#pragma unroll
    for (int p = 0; p < 8; p++)
        asm volatile("cp.async.cg.shared.global [%0], [%1], 16;"
                     :: "r"(bdst + (uint32_t)(8 * p) * BPITCH),
                        "l"(bsrc + (size_t)(8 * p) * NN));
    asm volatile("cp.async.commit_group;");
    asm volatile("cp.async.wait_group 0;");

    ChunkBuf A0, A1;
    load_chunk(gp0, sp0, s2p, 0, A0);
    __syncthreads();

    int c = 0;
    for (int sb = 0; sb < NCH / SBCH; sb++) {
        if (sb + 1 < NCH / SBCH) {
            int jblk = (sb + 1) * (SBCH * 32);
            uint32_t bd = bdst + (uint32_t)((sb + 1) & 1) * BBYTES;
#pragma unroll
            for (int p = 0; p < 8; p++)
                asm volatile("cp.async.cg.shared.global [%0], [%1], 16;"
                             :: "r"(bd + (uint32_t)(8 * p) * BPITCH),
                                "l"(bsrc + (size_t)(8 * p) * NN + jblk));
            asm volatile("cp.async.commit_group;");
        }

        uint32_t ldb = ldb0 + (uint32_t)(sb & 1) * BBYTES;
#pragma unroll 2
        for (int cc = 0; cc < SBCH; cc += 2) {
            proc_chunk(c,     A0, A1, gp0, sp0, s2p, sts0, lda0, ldb, s1v, bnv, dloc, acc);
            proc_chunk(c + 1, A1, A0, gp0, sp0, s2p, sts0, lda0, ldb, s1v, bnv, dloc, acc);
            c += 2;
        }

        asm volatile("cp.async.wait_group 0;");
        __syncthreads();
    }

    // ---- epilogue ----
#pragma unroll
    for (int i = 0; i < 4; i++) {
        float v = dloc[i];
        v += __shfl_xor_sync(0xffffffffu, v, 1);
        v += __shfl_xor_sync(0xffffffffu, v, 2);
        v += __shfl_xor_sync(0xffffffffu, v, 4);
        dloc[i] = v;
    }
    if ((lane & 7) == 0) {
#pragma unroll
        for (int i = 0; i < 4; i++)
            g_den[q * NN + i0 + 16 * w + 4 * i + subrow] = dloc[i];
    }

    // numerator partials: c-frag layout (r = lane>>2, tg = lane&3)
    int r = lane >> 2, tg = lane & 3;
    int row0 = i0 + 16 * w + r;
    float* dst0 = g_num + ((size_t)q * NN + row0) * OUT_F;
    float* dst1 = g_num + ((size_t)q * NN + row0 + 8) * OUT_F;
#pragma unroll
    for (int t = 0; t < 8; t++) {
        int n0 = 8 * t + 2 * tg;
        *(float2*)(dst0 + n0) = make_float2(acc[t][0], acc[t][1]);
        *(float2*)(dst1 + n0) = make_float2(acc[t][2], acc[t][3]);
    }
}

// ---------------------------------------------------------------------------
// Combine split-K partials: out = elu(sum(n)/sum(d))
// ---------------------------------------------------------------------------
__global__ __launch_bounds__(256) void k_fin(float* __restrict__ out) {
    int idx = blockIdx.x * 256 + threadIdx.x;
    int row = idx >> 4, qq = idx & 15;
    float den = g_den[row] + g_den[NN + row] + g_den[2 * NN + row] + g_den[3 * NN + row];
    float inv = 1.0f / den;
    float4 n0 = *(const float4*)&g_num[(size_t)row * OUT_F + 4 * qq];
    float4 n1 = *(const float4*)&g_num[(size_t)(NN + row) * OUT_F + 4 * qq];
    float4 n2 = *(const float4*)&g_num[(size_t)(2 * NN + row) * OUT_F + 4 * qq];
    float4 n3 = *(const float4*)&g_num[(size_t)(3 * NN + row) * OUT_F + 4 * qq];
    float4 o;
    float v;
    v = (n0.x + n1.x + n2.x + n3.x) * inv; o.x = (v > 0.f) ? v : expm1f(v);
    v = (n0.y + n1.y + n2.y + n3.y) * inv; o.y = (v > 0.f) ? v : expm1f(v);
    v = (n0.z + n1.z + n2.z + n3.z) * inv; o.z = (v > 0.f) ? v : expm1f(v);
    v = (n0.w + n1.w + n2.w + n3.w) * inv; o.w = (v > 0.f) ? v : expm1f(v);
    *(float4*)&out[(size_t)row * OUT_F + 4 * qq] = o;
}

// ---------------------------------------------------------------------------
extern "C" void kernel_launch(void* const* d_in, const int* in_sizes, int n_in,
                              void* d_out, int out_size) {
    const float* geo  = (const float*)d_in[0];
    const float* sem  = (const float*)d_in[1];
    const float* feat = (const float*)d_in[2];
    const float* W    = (const float*)d_in[3];
    const float* a    = (const float*)d_in[4];
    float* out = (float*)d_out;

    cudaFuncSetAttribute(k_main, cudaFuncAttributeMaxDynamicSharedMemorySize, SMEMT);

    k_proj<<<NN / 16, 1024>>>(feat, W, a);
    k_max<<<1, 256>>>();
    k_main<<<256, 256, SMEMT>>>(geo, sem);
    k_fin<<<512, 256>>>(out);
}

// round 11
// speedup vs baseline: 1.6473x; 1.0175x over previous
#include <cuda_runtime.h>
#include <cuda_fp16.h>
#include <cstdint>
#include <math.h>

#define NN 8192
#define IN_F 128
#define OUT_F 64
#define ALPHA 0.2f
#define LOG2E 1.4426950408889634f
#define NCH 64             // 32-col chunks over a 2048-col quarter
#define SBCH 8             // chunks per B superblock (256 cols)
#define BPITCH 528         // B smem row pitch -> 16B rotation, conflict-free
#define BBYTES (64 * BPITCH)
#define SPITCH 80          // score tile pitch -> 16B rotation, conflict-free
#define SWARP (2 * 16 * SPITCH)      // per-warp double-buffered score tile
#define SMEMT (2 * BBYTES + 8 * SWARP)   // 88064 B -> 2 CTAs/SM

// ---------------- device scratch (allocation-free rule) ----------------
__device__ float  g_s1[NN];
__device__ float  g_s2[NN];
__device__ float  g_M;
__device__ __half g_hT[(size_t)OUT_F * NN];     // H^T fp16, [f][j]
__device__ float  g_num[(size_t)4 * NN * OUT_F];
__device__ float  g_den[4 * NN];

// ---------------------------------------------------------------------------
// Kernel A: h = feat @ W^T ; s1/s2 row scores ; g_hT = fp16(h)^T
// ---------------------------------------------------------------------------
__global__ __launch_bounds__(1024) void k_proj(const float* __restrict__ feat,
                                               const float* __restrict__ W,
                                               const float* __restrict__ a) {
    __shared__ float Ws[OUT_F][IN_F + 4];
    __shared__ float Fs[16][IN_F];
    __shared__ float red1[32], red2[32];
    __shared__ __half Ts[OUT_F][18];

    int tid = threadIdx.x;
    int i0  = blockIdx.x * 16;

    for (int t = tid; t < OUT_F * IN_F; t += 1024)
        Ws[t / IN_F][t % IN_F] = W[t];
    for (int t = tid; t < 16 * IN_F; t += 1024)
        Fs[t / IN_F][t % IN_F] = feat[(size_t)(i0 + t / IN_F) * IN_F + (t % IN_F)];
    __syncthreads();

    int f = tid & 63;
    int r = tid >> 6;
    float acc = 0.f;
#pragma unroll
    for (int k = 0; k < IN_F; k += 4) {
        float4 fv = *(const float4*)&Fs[r][k];
        float4 wv = *(const float4*)&Ws[f][k];
        acc += fv.x * wv.x + fv.y * wv.y + fv.z * wv.z + fv.w * wv.w;
    }

    Ts[f][r] = __float2half(acc);

    float t1 = acc * a[f];
    float t2 = acc * a[OUT_F + f];
#pragma unroll
    for (int off = 16; off; off >>= 1) {
        t1 += __shfl_xor_sync(0xffffffffu, t1, off);
        t2 += __shfl_xor_sync(0xffffffffu, t2, off);
    }
    int w = tid >> 5;
    if ((tid & 31) == 0) { red1[w] = t1; red2[w] = t2; }
    __syncthreads();
    if (tid < 16) {
        g_s1[i0 + tid] = red1[2 * tid] + red1[2 * tid + 1];
        g_s2[i0 + tid] = red2[2 * tid] + red2[2 * tid + 1];
    }
    if (tid < 512) {
        int ff = tid >> 3, u = tid & 7;
        __half2 pk = __halves2half2(Ts[ff][2 * u], Ts[ff][2 * u + 1]);
        *(__half2*)&g_hT[(size_t)ff * NN + i0 + 2 * u] = pk;
    }
}

// ---------------------------------------------------------------------------
// Kernel B: g_M = max_j s2[j]
// ---------------------------------------------------------------------------
__global__ __launch_bounds__(256) void k_max() {
    __shared__ float red[8];
    int tid = threadIdx.x;
    float m = -1e30f;
    for (int i = tid; i < NN; i += 256) m = fmaxf(m, g_s2[i]);
#pragma unroll
    for (int off = 16; off; off >>= 1)
        m = fmaxf(m, __shfl_xor_sync(0xffffffffu, m, off));
    if ((tid & 31) == 0) red[tid >> 5] = m;
    __syncthreads();
    if (tid == 0) {
        float mm = red[0];
#pragma unroll
        for (int i = 1; i < 8; i++) mm = fmaxf(mm, red[i]);
        g_M = mm;
    }
}

// ---------------------------------------------------------------------------
// Main kernel. 256 CTAs (64 row-tiles x 4 quarters) x 256 threads, 2 CTAs/SM.
// Per-warp chunk ROTATION within each superblock desynchronizes the warps'
// LDG bursts -> smooth DRAM demand instead of phase-locked bursts.
// ---------------------------------------------------------------------------
struct ChunkBuf {
    float4 G[4];
    float4 S[4];
    float4 Z;
};

__device__ __forceinline__ void load_chunk(const float* __restrict__ gp0,
                                           const float* __restrict__ sp0,
                                           const float* __restrict__ s2p,
                                           int c, ChunkBuf& b) {
    size_t off = (size_t)c * 32;
#pragma unroll
    for (int i = 0; i < 4; i++) {
        b.G[i] = __ldcs((const float4*)(gp0 + off + (size_t)(4 * i) * NN));
        b.S[i] = __ldcs((const float4*)(sp0 + off + (size_t)(4 * i) * NN));
    }
    b.Z = *(const float4*)(s2p + off);
}

__device__ __forceinline__ void mma16816(float* d, const uint32_t* a,
                                         uint32_t b0, uint32_t b1) {
    asm volatile(
        "mma.sync.aligned.m16n8k16.row.col.f32.f16.f16.f32 "
        "{%0,%1,%2,%3},{%4,%5,%6,%7},{%8,%9},{%0,%1,%2,%3};"
        : "+f"(d[0]), "+f"(d[1]), "+f"(d[2]), "+f"(d[3])
        : "r"(a[0]), "r"(a[1]), "r"(a[2]), "r"(a[3]), "r"(b0), "r"(b1));
}

__device__ __forceinline__ void proc_chunk(int c, int cn, int par,
                                           ChunkBuf& cur, ChunkBuf& nxt,
                                           const float* gp0, const float* sp0,
                                           const float* s2p,
                                           uint32_t sts0, uint32_t lda0, uint32_t ldb,
                                           const float (&s1v)[4], const float (&bnv)[4],
                                           float (&dloc)[4], float (&acc)[8][4]) {
    // 1. prefetch next chunk's adjacency (coalesced LDG.128)
    load_chunk(gp0, sp0, s2p, cn, nxt);

    uint32_t bufo = (uint32_t)par * (16 * SPITCH);

    // 2. scores in coalesced layout (4 rows x 4 cols per thread) -> smem
    __half2 dh[4];
#pragma unroll
    for (int i = 0; i < 4; i++) {
        float4 g = cur.G[i], s = cur.S[i];
        float clx = (g.x + s.x) * LOG2E;
        float cly = (g.y + s.y) * LOG2E;
        float clz = (g.z + s.z) * LOG2E;
        float clw = (g.w + s.w) * LOG2E;
        float s1 = s1v[i], bn = bnv[i];
        float x0 = s1 + cur.Z.x, x1 = s1 + cur.Z.y;
        float x2 = s1 + cur.Z.z, x3 = s1 + cur.Z.w;
        float l0 = fmaxf(x0, ALPHA * x0), l1 = fmaxf(x1, ALPHA * x1);
        float l2 = fmaxf(x2, ALPHA * x2), l3 = fmaxf(x3, ALPHA * x3);
        float p0 = (clx > 0.f) ? exp2f(fmaf(l0, clx, -bn)) : 0.f;
        float p1 = (cly > 0.f) ? exp2f(fmaf(l1, cly, -bn)) : 0.f;
        float p2 = (clz > 0.f) ? exp2f(fmaf(l2, clz, -bn)) : 0.f;
        float p3 = (clw > 0.f) ? exp2f(fmaf(l3, clw, -bn)) : 0.f;
        __half2 lo = __floats2half2_rn(p0, p1);
        __half2 hi = __floats2half2_rn(p2, p3);
        dh[i] = __hadd2(lo, hi);
        asm volatile("st.shared.v2.b32 [%0], {%1,%2};"
                     :: "r"(sts0 + bufo + (uint32_t)(4 * i) * SPITCH),
                        "r"(*(uint32_t*)&lo), "r"(*(uint32_t*)&hi));
    }
#pragma unroll
    for (int i = 0; i < 4; i++) {
        float2 d = __half22float2(dh[i]);
        dloc[i] += d.x + d.y;
    }

    __syncwarp();

    // 3. A-frags via ldmatrix from own warp's tile
    uint32_t af[2][4];
    uint32_t la = lda0 + bufo;
#pragma unroll
    for (int kk = 0; kk < 2; kk++)
        asm volatile(
            "ldmatrix.sync.aligned.m8n8.x4.shared.b16 {%0,%1,%2,%3}, [%4];"
            : "=r"(af[kk][0]), "=r"(af[kk][1]), "=r"(af[kk][2]), "=r"(af[kk][3])
            : "r"(la + kk * 32));

    // 4. B-frags + 16 HMMA  (c & 7 = column-chunk within superblock)
    uint32_t bb = ldb + (uint32_t)(c & (SBCH - 1)) * 64;
#pragma unroll
    for (int kk = 0; kk < 2; kk++) {
#pragma unroll
        for (int t = 0; t < 4; t++) {
            uint32_t b0, b1, b2, b3;
            asm volatile(
                "ldmatrix.sync.aligned.m8n8.x4.shared.b16 {%0,%1,%2,%3}, [%4];"
                : "=r"(b0), "=r"(b1), "=r"(b2), "=r"(b3)
                : "r"(bb + (uint32_t)t * 16 * BPITCH + kk * 32));
            mma16816(acc[2 * t],     af[kk], b0, b1);
            mma16816(acc[2 * t + 1], af[kk], b2, b3);
        }
    }
}

__global__ __launch_bounds__(256, 2) void k_main(const float* __restrict__ geo,
                                                 const float* __restrict__ sem) {
    extern __shared__ __align__(16) char smem[];

    int tid = threadIdx.x, lane = tid & 31, w = tid >> 5;
    int rb = blockIdx.x >> 2, q = blockIdx.x & 3;
    int i0 = rb * 128, jbase = q * 2048;

    int subrow = lane >> 3, colseg = (lane & 7) * 4;

    const float* gp0 = geo + (size_t)(i0 + 16 * w + subrow) * NN + jbase + colseg;
    const float* sp0 = sem + (size_t)(i0 + 16 * w + subrow) * NN + jbase + colseg;
    const float* s2p = g_s2 + jbase + colseg;

    float Mv = g_M;
    float s1v[4], bnv[4];
#pragma unroll
    for (int i = 0; i < 4; i++) {
        s1v[i] = g_s1[i0 + 16 * w + 4 * i + subrow];
        bnv[i] = fmaxf(0.f, 2.f * (s1v[i] + Mv)) * LOG2E;
    }

    uint32_t smem0;
    asm("{ .reg .u64 t; cvta.to.shared.u64 t, %1; cvt.u32.u64 %0, t; }"
        : "=r"(smem0) : "l"(smem));
    uint32_t bbase = smem0;
    uint32_t sbuf  = smem0 + 2 * BBYTES + w * SWARP;

    uint32_t sts0 = sbuf + (uint32_t)subrow * SPITCH + (uint32_t)colseg * 2;
    uint32_t lda0 = sbuf + (uint32_t)(lane & 15) * SPITCH + (uint32_t)(lane >> 4) * 16;
    int ldrow = ((lane >> 4) & 1) * 8 + (lane & 7);
    int ldcol = ((lane >> 3) & 1) * 16;
    uint32_t ldb0 = bbase + (uint32_t)ldrow * BPITCH + ldcol;

    // B staging map
    int srow = tid >> 5, sseg = tid & 31;
    const __half* bsrc = g_hT + (size_t)srow * NN + jbase + sseg * 8;
    uint32_t bdst = bbase + (uint32_t)srow * BPITCH + sseg * 16;

    float acc[8][4];
#pragma unroll
    for (int i = 0; i < 8; i++)
#pragma unroll
        for (int j = 0; j < 4; j++) acc[i][j] = 0.f;
    float dloc[4] = {0.f, 0.f, 0.f, 0.f};

    // prologue: stage B superblock 0
#pragma unroll
    for (int p = 0; p < 8; p++)
        asm volatile("cp.async.cg.shared.global [%0], [%1], 16;"
                     :: "r"(bdst + (uint32_t)(8 * p) * BPITCH),
                        "l"(bsrc + (size_t)(8 * p) * NN));
    asm volatile("cp.async.commit_group;");
    asm volatile("cp.async.wait_group 0;");

    // prologue: warp w starts at chunk w (rotated) -> desynchronized bursts
    ChunkBuf A0, A1;
    load_chunk(gp0, sp0, s2p, w & 7, A0);
    __syncthreads();

    const int sbN = NCH / SBCH;   // 8
    for (int sb = 0; sb < sbN; sb++) {
        if (sb + 1 < sbN) {
            int jblk = (sb + 1) * (SBCH * 32);
            uint32_t bd = bdst + (uint32_t)((sb + 1) & 1) * BBYTES;
#pragma unroll
            for (int p = 0; p < 8; p++)
                asm volatile("cp.async.cg.shared.global [%0], [%1], 16;"
                             :: "r"(bd + (uint32_t)(8 * p) * BPITCH),
                                "l"(bsrc + (size_t)(8 * p) * NN + jblk));
            asm volatile("cp.async.commit_group;");
        }

        uint32_t ldb = ldb0 + (uint32_t)(sb & 1) * BBYTES;
#pragma unroll
        for (int cc = 0; cc < SBCH; cc++) {
            int c = sb * SBCH + ((cc + w) & 7);
            int ncc = cc + 1, nsb = sb;
            if (ncc == SBCH) { ncc = 0; nsb = sb + 1; }
            int cn = (nsb < sbN) ? (nsb * SBCH + ((ncc + w) & 7)) : 0;
            if (cc & 1)
                proc_chunk(c, cn, 1, A1, A0, gp0, sp0, s2p, sts0, lda0, ldb,
                           s1v, bnv, dloc, acc);
            else
                proc_chunk(c, cn, 0, A0, A1, gp0, sp0, s2p, sts0, lda0, ldb,
                           s1v, bnv, dloc, acc);
        }

        asm volatile("cp.async.wait_group 0;");
        __syncthreads();
    }

    // ---- epilogue ----
#pragma unroll
    for (int i = 0; i < 4; i++) {
        float v = dloc[i];
        v += __shfl_xor_sync(0xffffffffu, v, 1);
        v += __shfl_xor_sync(0xffffffffu, v, 2);
        v += __shfl_xor_sync(0xffffffffu, v, 4);
        dloc[i] = v;
    }
    if ((lane & 7) == 0) {
#pragma unroll
        for (int i = 0; i < 4; i++)
            g_den[q * NN + i0 + 16 * w + 4 * i + subrow] = dloc[i];
    }

    // numerator partials: c-frag layout (r = lane>>2, tg = lane&3)
    int r = lane >> 2, tg = lane & 3;
    int row0 = i0 + 16 * w + r;
    float* dst0 = g_num + ((size_t)q * NN + row0) * OUT_F;
    float* dst1 = g_num + ((size_t)q * NN + row0 + 8) * OUT_F;
#pragma unroll
    for (int t = 0; t < 8; t++) {
        int n0 = 8 * t + 2 * tg;
        *(float2*)(dst0 + n0) = make_float2(acc[t][0], acc[t][1]);
        *(float2*)(dst1 + n0) = make_float2(acc[t][2], acc[t][3]);
    }
}

// ---------------------------------------------------------------------------
// Combine split-K partials: out = elu(sum(n)/sum(d))
// Grid 1024x256, 2 floats/thread -> higher occupancy than the 512-block form.
// ---------------------------------------------------------------------------
__global__ __launch_bounds__(256) void k_fin(float* __restrict__ out) {
    int idx = blockIdx.x * 256 + threadIdx.x;     // 262144 threads
    int row = idx >> 5, qq = idx & 31;            // 32 threads/row, 2 floats
    float den = g_den[row] + g_den[NN + row] + g_den[2 * NN + row] + g_den[3 * NN + row];
    float inv = 1.0f / den;
    float2 n0 = *(const float2*)&g_num[(size_t)row * OUT_F + 2 * qq];
    float2 n1 = *(const float2*)&g_num[(size_t)(NN + row) * OUT_F + 2 * qq];
    float2 n2 = *(const float2*)&g_num[(size_t)(2 * NN + row) * OUT_F + 2 * qq];
    float2 n3 = *(const float2*)&g_num[(size_t)(3 * NN + row) * OUT_F + 2 * qq];
    float2 o;
    float v;
    v = (n0.x + n1.x + n2.x + n3.x) * inv; o.x = (v > 0.f) ? v : expm1f(v);
    v = (n0.y + n1.y + n2.y + n3.y) * inv; o.y = (v > 0.f) ? v : expm1f(v);
    *(float2*)&out[(size_t)row * OUT_F + 2 * qq] = o;
}

// ---------------------------------------------------------------------------
extern "C" void kernel_launch(void* const* d_in, const int* in_sizes, int n_in,
                              void* d_out, int out_size) {
    const float* geo  = (const float*)d_in[0];
    const float* sem  = (const float*)d_in[1];
    const float* feat = (const float*)d_in[2];
    const float* W    = (const float*)d_in[3];
    const float* a    = (const float*)d_in[4];
    float* out = (float*)d_out;

    cudaFuncSetAttribute(k_main, cudaFuncAttributeMaxDynamicSharedMemorySize, SMEMT);

    k_proj<<<NN / 16, 1024>>>(feat, W, a);
    k_max<<<1, 256>>>();
    k_main<<<256, 256, SMEMT>>>(geo, sem);
    k_fin<<<1024, 256>>>(out);
}